// round 1
// baseline (speedup 1.0000x reference)
#include <cuda_runtime.h>
#include <cstdint>

#define BB 16
#define CC 768
#define TT 1024
#define STEPS 12
#define NNEG 10
#define COPIES 11
#define BT (BB*TT)  // 16384

// ---- scratch (static device globals; no runtime allocation) ----
__device__ float g_yT[(size_t)BB*TT*CC];          // [b][t][c]   (c contiguous)  ~50 MB
__device__ float g_Wt[(size_t)STEPS*CC*CC];       // [i][c][d]   (d contiguous)  ~28 MB
__device__ float g_proj[(size_t)STEPS*BT*CC];     // [i][b*T+t][d]               ~604 MB

// ---------------------------------------------------------------------------
// 1a. transpose y[b][c][t] -> yT[b][t][c]
// ---------------------------------------------------------------------------
__global__ void transpose_y_kernel(const float* __restrict__ y) {
    __shared__ float tile[32][33];
    int b  = blockIdx.z;
    int c0 = blockIdx.y * 32;
    int t0 = blockIdx.x * 32;
    int tx = threadIdx.x, ty = threadIdx.y;   // block (32,8)
    #pragma unroll
    for (int j = 0; j < 32; j += 8)
        tile[ty + j][tx] = y[((size_t)b*CC + c0 + ty + j)*TT + t0 + tx];
    __syncthreads();
    #pragma unroll
    for (int j = 0; j < 32; j += 8)
        g_yT[((size_t)b*TT + t0 + ty + j)*CC + c0 + tx] = tile[tx][ty + j];
}

// ---------------------------------------------------------------------------
// 1b. repack W[c][d][i] -> Wt[i][c][d]
// ---------------------------------------------------------------------------
__global__ void repack_w_kernel(const float* __restrict__ W) {
    size_t o = (size_t)blockIdx.x * blockDim.x + threadIdx.x;
    if (o >= (size_t)STEPS*CC*CC) return;
    int d = (int)(o % CC);
    int c = (int)((o / CC) % CC);
    int i = (int)(o / ((size_t)CC*CC));
    g_Wt[o] = W[((size_t)c*CC + d)*STEPS + i];
}

// ---------------------------------------------------------------------------
// 2. proj[i][m][d] = sum_c x[b][c][t] * Wt[i][c][d] + bias[d]
//    M=16384 (m=b*T+t), K=768, per-step N=768. Tiles: 128x64x16, 256 thr, 8x4.
// ---------------------------------------------------------------------------
#define BM 128
#define BN 64
#define BK 16

__global__ __launch_bounds__(256) void gemm_proj_kernel(
    const float* __restrict__ x, const float* __restrict__ bias)
{
    __shared__ float As[BK][BM];
    __shared__ float Bs[BK][BN];
    const int i  = blockIdx.z;
    const int m0 = blockIdx.y * BM;
    const int n0 = blockIdx.x * BN;
    const int b  = m0 / TT;              // BM divides T -> tile never crosses b
    const int t0 = m0 % TT;
    const int tid = threadIdx.x;
    const int ty = tid >> 4;             // 0..15  (8 rows each)
    const int tx = tid & 15;             // 0..15  (4 cols each)

    float acc[8][4];
    #pragma unroll
    for (int r = 0; r < 8; r++)
        #pragma unroll
        for (int j = 0; j < 4; j++) acc[r][j] = 0.f;

    const float* xb = x + (size_t)b*CC*TT + t0;          // x[b][c][t0+..]
    const float* wt = g_Wt + (size_t)i*CC*CC + n0;       // Wt[i][c][n0+..]

    const int lm = tid & 127;            // A-load row
    const int lk = tid >> 7;             // A-load k-half

    for (int c0 = 0; c0 < CC; c0 += BK) {
        #pragma unroll
        for (int kk = 0; kk < 8; kk++) {
            int k = lk*8 + kk;
            As[k][lm] = xb[(size_t)(c0 + k)*TT + lm];
        }
        #pragma unroll
        for (int e = 0; e < 4; e++) {
            int f = tid + e*256;         // 0..1023
            int k = f >> 6, n = f & 63;
            Bs[k][n] = wt[(size_t)(c0 + k)*CC + n];
        }
        __syncthreads();
        #pragma unroll
        for (int k = 0; k < BK; k++) {
            const float4* a4 = reinterpret_cast<const float4*>(&As[k][ty*8]);
            float4 a0 = a4[0], a1 = a4[1];
            float4 bv = *reinterpret_cast<const float4*>(&Bs[k][tx*4]);
            float a[8] = {a0.x,a0.y,a0.z,a0.w,a1.x,a1.y,a1.z,a1.w};
            float bb[4] = {bv.x,bv.y,bv.z,bv.w};
            #pragma unroll
            for (int r = 0; r < 8; r++)
                #pragma unroll
                for (int j = 0; j < 4; j++)
                    acc[r][j] += a[r]*bb[j];
        }
        __syncthreads();
    }

    float bz[4];
    #pragma unroll
    for (int j = 0; j < 4; j++) bz[j] = bias[n0 + tx*4 + j];

    float* out = g_proj + ((size_t)i*BT + m0)*CC + n0;
    #pragma unroll
    for (int r = 0; r < 8; r++) {
        float4 v = make_float4(acc[r][0]+bz[0], acc[r][1]+bz[1],
                               acc[r][2]+bz[2], acc[r][3]+bz[3]);
        *reinterpret_cast<float4*>(out + (size_t)(ty*8 + r)*CC + tx*4) = v;
    }
}

// ---------------------------------------------------------------------------
// 3. logits: one warp per row (i,t,b).
//    p[row][n] = sum_c proj[i][b*T+t][c] * tgt_n[c]
//    tgt_0 = yT[b*T+t+off], tgt_{1+n} = yT[neg_idxs[b][n*T + t+off]]
// ---------------------------------------------------------------------------
__global__ __launch_bounds__(256) void dot_kernel(
    const int* __restrict__ neg, float* __restrict__ outp, int total_rows)
{
    int w = (int)(((size_t)blockIdx.x * blockDim.x + threadIdx.x) >> 5);
    int lane = threadIdx.x & 31;
    if (w >= total_rows) return;

    // decode (i, t, b) from row id: rows_i = (T-1-i)*B, order i -> t -> b
    int r = w, i = 0;
    for (int ii = 0; ii < STEPS; ii++) {
        int rows = (TT - 1 - ii) * BB;
        if (r < rows) { i = ii; break; }
        r -= rows;
    }
    const int t  = r / BB;
    const int b  = r % BB;
    const int t2 = t + i + 1;

    const float4* pr = reinterpret_cast<const float4*>(
        g_proj + ((size_t)i*BT + (size_t)b*TT + t)*CC);
    const float4* tg[COPIES];
    tg[0] = reinterpret_cast<const float4*>(g_yT + ((size_t)b*TT + t2)*CC);
    #pragma unroll
    for (int n = 0; n < NNEG; n++) {
        int g = neg[b*(NNEG*TT) + n*TT + t2];
        tg[1+n] = reinterpret_cast<const float4*>(g_yT + (size_t)g*CC);
    }

    float acc[COPIES];
    #pragma unroll
    for (int n = 0; n < COPIES; n++) acc[n] = 0.f;

    #pragma unroll
    for (int c4 = lane, it = 0; it < CC/(32*4); c4 += 32, it++) {
        float4 p = __ldcs(pr + c4);      // streaming: proj is read exactly once
        #pragma unroll
        for (int n = 0; n < COPIES; n++) {
            float4 tv = __ldg(tg[n] + c4);
            acc[n] += p.x*tv.x + p.y*tv.y + p.z*tv.z + p.w*tv.w;
        }
    }

    #pragma unroll
    for (int n = 0; n < COPIES; n++) {
        #pragma unroll
        for (int s = 16; s > 0; s >>= 1)
            acc[n] += __shfl_xor_sync(0xffffffffu, acc[n], s);
    }
    if (lane == 0) {
        float* o = outp + (size_t)w * COPIES;
        #pragma unroll
        for (int n = 0; n < COPIES; n++) o[n] = acc[n];
    }
}

// ---------------------------------------------------------------------------
extern "C" void kernel_launch(void* const* d_in, const int* in_sizes, int n_in,
                              void* d_out, int out_size) {
    const float* x    = (const float*)d_in[0];
    const float* y    = (const float*)d_in[1];
    const float* W    = (const float*)d_in[2];
    const float* bias = (const float*)d_in[3];
    const int*   neg  = (const int*)d_in[4];
    float* out = (float*)d_out;

    // total logits rows: sum_i (T-1-i)*B, i=0..11
    int total_rows = 0;
    for (int i = 0; i < STEPS; i++) total_rows += (TT - 1 - i) * BB;  // 195360
    size_t npred = (size_t)total_rows * COPIES;                        // 2148960

    // zero the labels tail (int32 zeros == float 0.0f bit pattern)
    if ((size_t)out_size > npred)
        cudaMemsetAsync((char*)d_out + npred * 4, 0, ((size_t)out_size - npred) * 4);

    {   // y transpose
        dim3 g(TT/32, CC/32, BB), blk(32, 8);
        transpose_y_kernel<<<g, blk>>>(y);
    }
    {   // W repack
        size_t n = (size_t)STEPS*CC*CC;
        repack_w_kernel<<<(unsigned)((n + 255)/256), 256>>>(W);
    }
    {   // projection GEMM
        dim3 g(CC/BN, BT/BM, STEPS);   // (12, 128, 12)
        gemm_proj_kernel<<<g, 256>>>(x, bias);
    }
    {   // logits
        int warps = total_rows;
        int blocks = (warps + 7) / 8;  // 8 warps / block
        dot_kernel<<<blocks, 256>>>(neg, out, total_rows);
    }
}

// round 4
// speedup vs baseline: 2.1902x; 2.1902x over previous
#include <cuda_runtime.h>
#include <cuda_bf16.h>
#include <cstdint>

#define BB 16
#define CC 768
#define TT 1024
#define STEPS 12
#define NNEG 10
#define COPIES 11
#define BT (BB*TT)  // 16384

// ---- scratch (static device globals; no runtime allocation) ----
__device__ float g_yT[(size_t)BB*TT*CC];                  // [b][t][c]
__device__ float g_proj[(size_t)STEPS*BT*CC];             // [i][m][d]
__device__ __nv_bfloat16 g_xhi[(size_t)BT*CC];            // [m][c]
__device__ __nv_bfloat16 g_xlo[(size_t)BT*CC];
__device__ __nv_bfloat16 g_whi[(size_t)STEPS*CC*CC];      // [(i*768+d)][c]
__device__ __nv_bfloat16 g_wlo[(size_t)STEPS*CC*CC];

// ============================ asm helpers ============================
__device__ __forceinline__ uint32_t smem_u32(const void* p) {
    uint32_t a;
    asm("{ .reg .u64 t; cvta.to.shared.u64 t, %1; cvt.u32.u64 %0, t; }" : "=r"(a) : "l"(p));
    return a;
}

__device__ __forceinline__ void cp_async16(uint32_t saddr, const void* gaddr) {
    asm volatile("cp.async.cg.shared.global [%0], [%1], 16;" :: "r"(saddr), "l"(gaddr));
}
__device__ __forceinline__ void cp_commit() {
    asm volatile("cp.async.commit_group;" ::: "memory");
}
__device__ __forceinline__ void cp_wait1() {
    asm volatile("cp.async.wait_group 1;" ::: "memory");
}

__device__ __forceinline__ void ldmx4(uint32_t* r, uint32_t addr) {
    asm volatile("ldmatrix.sync.aligned.m8n8.x4.shared.b16 {%0,%1,%2,%3}, [%4];"
        : "=r"(r[0]), "=r"(r[1]), "=r"(r[2]), "=r"(r[3]) : "r"(addr));
}

__device__ __forceinline__ void mma16816(float* d, const uint32_t* a, const uint32_t* b) {
    asm volatile("mma.sync.aligned.m16n8k16.row.col.f32.bf16.bf16.f32 "
        "{%0,%1,%2,%3}, {%4,%5,%6,%7}, {%8,%9}, {%0,%1,%2,%3};"
        : "+f"(d[0]), "+f"(d[1]), "+f"(d[2]), "+f"(d[3])
        : "r"(a[0]), "r"(a[1]), "r"(a[2]), "r"(a[3]), "r"(b[0]), "r"(b[1]));
}

// swizzled byte offset for a (row, 16B-chunk) element of a [rows][32] bf16 tile
// rows are 64B; two rows share a 128B line; Swizzle<3,4,3> on the line.
__device__ __forceinline__ uint32_t sw_off(int r, int c) {
    uint32_t bo = r*64 + c*16;
    return bo ^ (((bo >> 7) & 7) << 4);
}

// ============================ prepack kernels ============================
__global__ void transpose_y_kernel(const float* __restrict__ y) {
    __shared__ float tile[32][33];
    int b = blockIdx.z, c0 = blockIdx.y * 32, t0 = blockIdx.x * 32;
    int tx = threadIdx.x, ty = threadIdx.y;
    #pragma unroll
    for (int j = 0; j < 32; j += 8)
        tile[ty + j][tx] = y[((size_t)b*CC + c0 + ty + j)*TT + t0 + tx];
    __syncthreads();
    #pragma unroll
    for (int j = 0; j < 32; j += 8)
        g_yT[((size_t)b*TT + t0 + ty + j)*CC + c0 + tx] = tile[tx][ty + j];
}

__global__ void pack_x_kernel(const float* __restrict__ x) {
    __shared__ float tile[32][33];
    int b = blockIdx.z, c0 = blockIdx.y * 32, t0 = blockIdx.x * 32;
    int tx = threadIdx.x, ty = threadIdx.y;
    #pragma unroll
    for (int j = 0; j < 32; j += 8)
        tile[ty + j][tx] = x[((size_t)b*CC + c0 + ty + j)*TT + t0 + tx];
    __syncthreads();
    #pragma unroll
    for (int j = 0; j < 32; j += 8) {
        float v = tile[tx][ty + j];
        __nv_bfloat16 h = __float2bfloat16(v);
        __nv_bfloat16 l = __float2bfloat16(v - __bfloat162float(h));
        size_t o = ((size_t)b*TT + t0 + ty + j)*CC + c0 + tx;
        g_xhi[o] = h;
        g_xlo[o] = l;
    }
}

__global__ void pack_w_kernel(const float* __restrict__ W) {
    size_t o = (size_t)blockIdx.x * blockDim.x + threadIdx.x;
    if (o >= (size_t)STEPS*CC*CC) return;
    int c = (int)(o % CC);
    int d = (int)((o / CC) % CC);
    int i = (int)(o / ((size_t)CC*CC));
    float v = W[((size_t)c*CC + d)*STEPS + i];
    __nv_bfloat16 h = __float2bfloat16(v);
    __nv_bfloat16 l = __float2bfloat16(v - __bfloat162float(h));
    g_whi[o] = h;
    g_wlo[o] = l;
}

// ============================ HMMA GEMM ============================
// proj[i][m][d] = sum_c x[m][c]*W[i][d][c] + bias[d]
// Tile 128x128x32, 256 thr (2x4 warps, warp=64x32), 3-stage cp.async,
// bf16x3: hi*hi + hi*lo + lo*hi.
#define BM 128
#define BN 128
#define BK 32
#define KITERS (CC/BK)   // 24
#define TILE_B (BM*BK*2) // 8192 bytes per sub-tile
#define SA_H 0
#define SA_L (TILE_B)
#define SB_H (2*TILE_B)
#define SB_L (3*TILE_B)
#define STG  (4*TILE_B)  // 32768 per stage
#define SMEM_GEMM (3*STG) // 98304

__global__ __launch_bounds__(256, 1) void gemm_hmma_kernel(const float* __restrict__ bias)
{
    extern __shared__ char smem[];
    const uint32_t sbase = smem_u32(smem);
    const int tid = threadIdx.x;
    const int wid = tid >> 5, lane = tid & 31;
    const int n0 = blockIdx.x * BN;
    const int m0 = blockIdx.y * BM;
    const int stepi = blockIdx.z;
    const int wm = wid >> 2;     // 0..1
    const int wn = wid & 3;      // 0..3

    const __nv_bfloat16* gAh = g_xhi + (size_t)m0*CC;
    const __nv_bfloat16* gAl = g_xlo + (size_t)m0*CC;
    const __nv_bfloat16* gBh = g_whi + ((size_t)stepi*CC + n0)*CC;
    const __nv_bfloat16* gBl = g_wlo + ((size_t)stepi*CC + n0)*CC;

    // per-thread load slots: idx = tid + e*256; r = idx/4 (row), c = idx%4 (16B chunk)
    const int lr0 = tid >> 2, lc = tid & 3;

    auto load_stage = [&](int kt, int s) {
        const int k0 = kt * BK;
        const uint32_t sa = sbase + s*STG;
        #pragma unroll
        for (int e = 0; e < 2; e++) {
            int r = lr0 + e*64;
            uint32_t so = sw_off(r, lc);
            size_t go = (size_t)r*CC + k0 + lc*8;
            cp_async16(sa + SA_H + so, gAh + go);
            cp_async16(sa + SA_L + so, gAl + go);
            cp_async16(sa + SB_H + so, gBh + go);
            cp_async16(sa + SB_L + so, gBl + go);
        }
        cp_commit();
    };

    float acc[4][4][4];
    #pragma unroll
    for (int mt = 0; mt < 4; mt++)
        #pragma unroll
        for (int nt = 0; nt < 4; nt++)
            #pragma unroll
            for (int q = 0; q < 4; q++) acc[mt][nt][q] = 0.f;

    load_stage(0, 0);
    load_stage(1, 1);

    const int matid = lane >> 3, lrow = lane & 7;

    for (int kt = 0; kt < KITERS; kt++) {
        const int s = kt % 3;
        cp_wait1();
        __syncthreads();
        if (kt + 2 < KITERS) load_stage(kt + 2, (kt + 2) % 3);

        const uint32_t sa = sbase + s*STG;
        #pragma unroll
        for (int h = 0; h < 2; h++) {          // two k16 halves of BK=32
            const int cbase = h*2;
            uint32_t ah[4][4], al[4][4];
            #pragma unroll
            for (int mt = 0; mt < 4; mt++) {
                int m = wm*64 + mt*16 + ((matid & 1) ? 8 : 0) + lrow;
                int c = cbase + (matid >> 1);
                uint32_t so = sw_off(m, c);
                ldmx4(ah[mt], sa + SA_H + so);
                ldmx4(al[mt], sa + SA_L + so);
            }
            uint32_t bh[2][4], bl[2][4];
            #pragma unroll
            for (int np = 0; np < 2; np++) {
                int n = wn*32 + np*16 + ((matid >> 1) ? 8 : 0) + lrow;
                int c = cbase + (matid & 1);
                uint32_t so = sw_off(n, c);
                ldmx4(bh[np], sa + SB_H + so);
                ldmx4(bl[np], sa + SB_L + so);
            }
            #pragma unroll
            for (int mt = 0; mt < 4; mt++)
                #pragma unroll
                for (int nt = 0; nt < 4; nt++) {
                    const uint32_t* fh = &bh[nt >> 1][(nt & 1)*2];
                    const uint32_t* fl = &bl[nt >> 1][(nt & 1)*2];
                    mma16816(acc[mt][nt], ah[mt], fh);
                    mma16816(acc[mt][nt], ah[mt], fl);
                    mma16816(acc[mt][nt], al[mt], fh);
                }
        }
    }

    // epilogue: d0,d1 -> (row, col..col+1); d2,d3 -> (row+8, col..col+1)
    const int mrow = wm*64 + (lane >> 2);
    const int ncol = wn*32 + (lane & 3)*2;
    #pragma unroll
    for (int nt = 0; nt < 4; nt++) {
        const int col = ncol + nt*8;
        const float b0 = bias[n0 + col], b1 = bias[n0 + col + 1];
        #pragma unroll
        for (int mt = 0; mt < 4; mt++) {
            float* o = g_proj + ((size_t)stepi*BT + m0 + mrow + mt*16)*CC + n0 + col;
            *reinterpret_cast<float2*>(o) =
                make_float2(acc[mt][nt][0] + b0, acc[mt][nt][1] + b1);
            *reinterpret_cast<float2*>(o + 8*CC) =
                make_float2(acc[mt][nt][2] + b0, acc[mt][nt][3] + b1);
        }
    }
}

// ============================ logits dot kernel ============================
__global__ __launch_bounds__(256) void dot_kernel(
    const int* __restrict__ neg, float* __restrict__ outp, int total_rows)
{
    int w = (int)(((size_t)blockIdx.x * blockDim.x + threadIdx.x) >> 5);
    int lane = threadIdx.x & 31;
    if (w >= total_rows) return;

    int r = w, i = 0;
    for (int ii = 0; ii < STEPS; ii++) {
        int rows = (TT - 1 - ii) * BB;
        if (r < rows) { i = ii; break; }
        r -= rows;
    }
    const int t  = r / BB;
    const int b  = r % BB;
    const int t2 = t + i + 1;

    const float4* pr = reinterpret_cast<const float4*>(
        g_proj + ((size_t)i*BT + (size_t)b*TT + t)*CC);
    const float4* tg[COPIES];
    tg[0] = reinterpret_cast<const float4*>(g_yT + ((size_t)b*TT + t2)*CC);
    #pragma unroll
    for (int n = 0; n < NNEG; n++) {
        int g = neg[b*(NNEG*TT) + n*TT + t2];
        tg[1+n] = reinterpret_cast<const float4*>(g_yT + (size_t)g*CC);
    }

    float acc[COPIES];
    #pragma unroll
    for (int n = 0; n < COPIES; n++) acc[n] = 0.f;

    #pragma unroll
    for (int c4 = lane, it = 0; it < CC/(32*4); c4 += 32, it++) {
        float4 p = __ldcs(pr + c4);
        #pragma unroll
        for (int n = 0; n < COPIES; n++) {
            float4 tv = __ldg(tg[n] + c4);
            acc[n] += p.x*tv.x + p.y*tv.y + p.z*tv.z + p.w*tv.w;
        }
    }

    #pragma unroll
    for (int n = 0; n < COPIES; n++) {
        #pragma unroll
        for (int s = 16; s > 0; s >>= 1)
            acc[n] += __shfl_xor_sync(0xffffffffu, acc[n], s);
    }
    if (lane == 0) {
        float* o = outp + (size_t)w * COPIES;
        #pragma unroll
        for (int n = 0; n < COPIES; n++) o[n] = acc[n];
    }
}

// ============================ host ============================
extern "C" void kernel_launch(void* const* d_in, const int* in_sizes, int n_in,
                              void* d_out, int out_size) {
    const float* x    = (const float*)d_in[0];
    const float* y    = (const float*)d_in[1];
    const float* W    = (const float*)d_in[2];
    const float* bias = (const float*)d_in[3];
    const int*   neg  = (const int*)d_in[4];
    float* out = (float*)d_out;

    int total_rows = 0;
    for (int i = 0; i < STEPS; i++) total_rows += (TT - 1 - i) * BB;  // 195360
    size_t npred = (size_t)total_rows * COPIES;

    if ((size_t)out_size > npred)
        cudaMemsetAsync((char*)d_out + npred * 4, 0, ((size_t)out_size - npred) * 4);

    {   // y transpose (for dot kernel)
        dim3 g(TT/32, CC/32, BB), blk(32, 8);
        transpose_y_kernel<<<g, blk>>>(y);
    }
    {   // x pack (bf16 hi/lo, transposed)
        dim3 g(TT/32, CC/32, BB), blk(32, 8);
        pack_x_kernel<<<g, blk>>>(x);
    }
    {   // W pack
        size_t n = (size_t)STEPS*CC*CC;
        pack_w_kernel<<<(unsigned)((n + 255)/256), 256>>>(W);
    }
    {   // HMMA GEMM
        static bool attr_set = false;
        if (!attr_set) {
            cudaFuncSetAttribute(gemm_hmma_kernel,
                                 cudaFuncAttributeMaxDynamicSharedMemorySize, SMEM_GEMM);
            attr_set = true;
        }
        dim3 g(CC/BN, BT/BM, STEPS);   // (6, 128, 12)
        gemm_hmma_kernel<<<g, 256, SMEM_GEMM>>>(bias);
    }
    {   // logits
        int blocks = (total_rows + 7) / 8;
        dot_kernel<<<blocks, 256>>>(neg, out, total_rows);
    }
}